// round 8
// baseline (speedup 1.0000x reference)
#include <cuda_runtime.h>
#include <cstdint>

// CCN promotion layer, persistent-contiguous: 8 blocks/SM, each block owns a
// contiguous run of nodes and per node does: zero 48KB -> sync -> overwrite.
//   - per-block store stream is strictly linear (memset-like TLB locality)
//   - overwrites hit L2 lines zeroed <=48KB earlier -> merged, no DRAM RMW
//   - no wave transitions (1184 CTAs total instead of 20000)
// NOTE: default STG.128 only — R6 measured __stcs dropping 6.9 -> 4.9 TB/s.
//
// tensors: [N, 3] f32 ; neigh: [N, 16] i32 (sorted per row)
// out = concat( promotions [N,16,16,16,3] f32 , new_parts [N,16] as f32 )
// promotions[n,c,a,b,s] = (nb[a]==nb[c] && nb[b]==nb[c]) ? tensors[nb[c]][s] : 0

static constexpr int D = 16;
static constexpr int F = 3;
static constexpr int PER_NODE    = D * D * D * F;      // 12288 floats
static constexpr int PER_NODE_V4 = PER_NODE / 4;       // 3072 float4
static constexpr int THREADS     = 256;
static constexpr int V4_PER_THR  = PER_NODE_V4 / THREADS;  // 12
static constexpr int BLOCKS      = 148 * 8;            // persistent grid

__global__ __launch_bounds__(THREADS, 8)
void ccn_persistent_kernel(const float* __restrict__ tensors,
                           const int*   __restrict__ neigh,
                           float*       __restrict__ out,
                           float*       __restrict__ out_parts,
                           int N, int write_parts)
{
    const int t = threadIdx.x;

    // contiguous node range for this block
    const int chunk   = (N + gridDim.x - 1) / gridDim.x;
    const int n_begin = blockIdx.x * chunk;
    const int n_end   = (n_begin + chunk < N) ? (n_begin + chunk) : N;

    const float4 z = make_float4(0.f, 0.f, 0.f, 0.f);

    for (int n = n_begin; n < n_end; n++) {
        // ---- warp 0: gather for this node; loads issue before the zero
        //      stores below so their latency hides under the STG stream.
        int      my = 0;
        unsigned m  = 0u;
        float    f0 = 0.f, f1 = 0.f, f2 = 0.f;
        if (t < D) {
            my = neigh[n * D + t];
            m  = __match_any_sync(0x0000FFFFu, my) & 0xFFFFu;
            f0 = tensors[my * F + 0];
            f1 = tensors[my * F + 1];
            f2 = tensors[my * F + 2];
            if (write_parts)
                out_parts[n * D + t] = (float)my;   // exact: ids < 2^24
        }

        // ---- zero this node's 48KB region, pure default STG.128
        float4* out4 = reinterpret_cast<float4*>(out) + (size_t)n * PER_NODE_V4;
        #pragma unroll
        for (int k = 0; k < V4_PER_THR; k++)
            out4[t + k * THREADS] = z;

        __syncthreads();   // zeros visible before warp 0 overwrites

        // ---- warp 0: overwrite nonzeros (merge into just-zeroed L2 lines)
        if (t < D) {
            float* base = out + (size_t)n * PER_NODE + t * (D * D * F);

            if (__popc(m) == 1) {
                // common case: only (a,b) = (c,c)
                float* p = base + (t * D + t) * F;
                p[0] = f0; p[1] = f1; p[2] = f2;
            } else {
                unsigned ma = m;
                while (ma) {
                    int a = __ffs(ma) - 1; ma &= ma - 1;
                    unsigned mb = m;
                    while (mb) {
                        int b = __ffs(mb) - 1; mb &= mb - 1;
                        float* p = base + (a * D + b) * F;
                        p[0] = f0; p[1] = f1; p[2] = f2;
                    }
                }
            }
        }
        // no trailing sync needed: next iteration touches disjoint addresses,
        // and warp 0's own program order covers its overwrite-then-zero.
    }
}

extern "C" void kernel_launch(void* const* d_in, const int* in_sizes, int n_in,
                              void* d_out, int out_size)
{
    const float* tensors = (const float*)d_in[0];
    const int*   neigh   = (const int*)d_in[1];
    float*       out     = (float*)d_out;

    const int N = in_sizes[1] / D;
    const long long promo_elems = (long long)N * PER_NODE;
    const long long tail = (long long)out_size - promo_elems;
    const int write_parts = (tail == (long long)N * D) ? 1 : 0;
    float* out_parts = out + promo_elems;

    const int blocks = (BLOCKS < N) ? BLOCKS : N;
    ccn_persistent_kernel<<<blocks, THREADS>>>(tensors, neigh, out, out_parts,
                                               N, write_parts);
}

// round 9
// speedup vs baseline: 1.2133x; 1.2133x over previous
#include <cuda_runtime.h>
#include <cstdint>

// CCN promotion layer, fully fused: one block per node.  (R5 design — FINAL.)
//   phase 1: zero the node's 48KB promotions region (12 x default STG.128 per
//            thread, contiguous per-block layout -> memset-like page locality)
//   phase 2: warp 0 overwrites the ~48 nonzero floats (L2-merged, no DRAM RMW)
//
// Measured 136.4us / 6.95 TB/s store rate = ~99% of the chip's memset-path
// ceiling (~7.0 TB/s, measured via cudaMemsetAsync in R4). Output traffic
// (983 MB) is mandatory and minimal, so this sits on the HBM-store roofline.
//
// Alternatives measured and rejected:
//   R1 fused per-element ALU decode:      2.7 TB/s (IMAD-bound stores)
//   R4 memset + separate scatter pass:    160us (scatter pass pays DRAM RMW)
//   R6 __stcs streaming stores:           4.9 TB/s (L1tex becomes binding @88%)
//   R8 persistent loop w/ internal BAR:   5.8 TB/s (barrier couples warps)
//
// tensors: [N, 3] f32 ; neigh: [N, 16] i32 (sorted per row)
// out = concat( promotions [N,16,16,16,3] f32 , new_parts [N,16] as f32 )
// promotions[n,c,a,b,s] = (nb[a]==nb[c] && nb[b]==nb[c]) ? tensors[nb[c]][s] : 0

static constexpr int D = 16;
static constexpr int F = 3;
static constexpr int PER_NODE    = D * D * D * F;      // 12288 floats
static constexpr int PER_NODE_V4 = PER_NODE / 4;       // 3072 float4
static constexpr int THREADS     = 256;
static constexpr int V4_PER_THR  = PER_NODE_V4 / THREADS;  // 12

__global__ __launch_bounds__(THREADS, 8)
void ccn_fused_kernel(const float* __restrict__ tensors,
                      const int*   __restrict__ neigh,
                      float*       __restrict__ out,
                      float*       __restrict__ out_parts,
                      int N, int write_parts)
{
    const int n = blockIdx.x;
    const int t = threadIdx.x;

    // ---- warp 0: start the gather chain early (loads overlap zero stores)
    int      my = 0;
    unsigned m  = 0u;
    float    f0 = 0.f, f1 = 0.f, f2 = 0.f;
    if (t < D) {
        my = neigh[n * D + t];
        // equality mask among lanes 0..15 in one instruction
        m = __match_any_sync(0x0000FFFFu, my) & 0xFFFFu;
        f0 = tensors[my * F + 0];
        f1 = tensors[my * F + 1];
        f2 = tensors[my * F + 2];
        if (write_parts)
            out_parts[n * D + t] = (float)my;   // exact: ids < 2^24
    }

    // ---- phase 1: zero this node's region, pure default STG.128
    float4* out4 = reinterpret_cast<float4*>(out) + (size_t)n * PER_NODE_V4;
    const float4 z = make_float4(0.f, 0.f, 0.f, 0.f);
    #pragma unroll
    for (int k = 0; k < V4_PER_THR; k++)
        out4[t + k * THREADS] = z;

    __syncthreads();   // block-level fence: zeros visible before overwrites

    // ---- phase 2: overwrite nonzeros (hits just-zeroed L2 lines -> merged)
    if (t < D) {
        float* base = out + (size_t)n * PER_NODE + t * (D * D * F);  // row c = t

        if (__popc(m) == 1) {
            // common case: only (a,b) = (c,c)
            float* p = base + (t * D + t) * F;
            p[0] = f0; p[1] = f1; p[2] = f2;
        } else {
            unsigned ma = m;
            while (ma) {
                int a = __ffs(ma) - 1; ma &= ma - 1;
                unsigned mb = m;
                while (mb) {
                    int b = __ffs(mb) - 1; mb &= mb - 1;
                    float* p = base + (a * D + b) * F;
                    p[0] = f0; p[1] = f1; p[2] = f2;
                }
            }
        }
    }
}

extern "C" void kernel_launch(void* const* d_in, const int* in_sizes, int n_in,
                              void* d_out, int out_size)
{
    const float* tensors = (const float*)d_in[0];
    const int*   neigh   = (const int*)d_in[1];
    float*       out     = (float*)d_out;

    const int N = in_sizes[1] / D;
    const long long promo_elems = (long long)N * PER_NODE;
    const long long tail = (long long)out_size - promo_elems;
    const int write_parts = (tail == (long long)N * D) ? 1 : 0;
    float* out_parts = out + promo_elems;

    ccn_fused_kernel<<<N, THREADS>>>(tensors, neigh, out, out_parts,
                                     N, write_parts);
}